// round 1
// baseline (speedup 1.0000x reference)
#include <cuda_runtime.h>

#define HH 1024
#define WW 1024
#define BATCH 16
#define NIMG (HH*WW)
#define NTEN (BATCH*NIMG)          // 16,777,216 floats per tensor
#define TX 128
#define TY 16
#define THREADS 256
#define SX (TX+4)                  // 132
#define SY (TY+4)                  // 20
#define MX (TX+2)                  // 130
#define MY (TY+2)                  // 18

// Ping-pong scratch: each buffer holds BOTH tensors' skeleton state.
__device__ float g_buf0[2*NTEN];
__device__ float g_buf1[2*NTEN];
// acc[0]=sum(skelP*gt) acc[1]=sum(skelP) acc[2]=sum(skelG*pred) acc[3]=sum(skelG)
__device__ double g_acc[4];

__device__ __forceinline__ float finf()  { return __int_as_float(0x7f800000); }
__device__ __forceinline__ float fninf() { return __int_as_float(0xff800000); }

__global__ void zero_acc_kernel() {
    if (threadIdx.x < 4) g_acc[threadIdx.x] = 0.0;
}

// Load x tile (+inf outside image, correct pad for min-pool) and compute the
// 3x3 min-pool into sm (-inf outside image, correct pad for the max-pool).
__device__ __forceinline__ void load_and_minpool(const float* __restrict__ src,
                                                 float* sx, float* sm,
                                                 int x0, int y0)
{
    const int tid = threadIdx.x;
    const int txx = tid & 31, tyy = tid >> 5;

    for (int r = tyy; r < SY; r += 8) {
        int gy = y0 + r;
        bool vy = (gy >= 0) && (gy < HH);
        const float* row = src + gy * WW;
        #pragma unroll
        for (int c = txx; c < SX; c += 32) {
            int gx = x0 + c;
            float v = finf();
            if (vy && gx >= 0 && gx < WW) v = row[gx];
            sx[r*SX + c] = v;
        }
    }
    __syncthreads();

    for (int r = tyy; r < MY; r += 8) {
        int gy = y0 + 1 + r;
        bool vy = (gy >= 0) && (gy < HH);
        #pragma unroll
        for (int c = txx; c < MX; c += 32) {
            int gx = x0 + 1 + c;
            float mn = fninf();
            if (vy && gx >= 0 && gx < WW) {
                const float* p = sx + r*SX + c;
                mn = p[0];
                mn = fminf(mn, p[1]);        mn = fminf(mn, p[2]);
                mn = fminf(mn, p[SX+0]);     mn = fminf(mn, p[SX+1]);   mn = fminf(mn, p[SX+2]);
                mn = fminf(mn, p[2*SX+0]);   mn = fminf(mn, p[2*SX+1]); mn = fminf(mn, p[2*SX+2]);
            }
            sm[r*MX + c] = mn;
        }
    }
    __syncthreads();
}

__device__ __forceinline__ float skel_out(const float* sx, const float* sm, int r, int c)
{
    const float* p = sm + r*MX + c;
    float mx = p[0];
    mx = fmaxf(mx, p[1]);        mx = fmaxf(mx, p[2]);
    mx = fmaxf(mx, p[MX+0]);     mx = fmaxf(mx, p[MX+1]);   mx = fmaxf(mx, p[MX+2]);
    mx = fmaxf(mx, p[2*MX+0]);   mx = fmaxf(mx, p[2*MX+1]); mx = fmaxf(mx, p[2*MX+2]);
    float mc = p[MX+1];                      // min_pool at center
    float contour = fmaxf(mx - mc, 0.0f);
    float xc = sx[(r+2)*SX + (c+2)];         // x at center
    return fmaxf(xc - contour, 0.0f);
}

// One soft-skeletonize iteration for both tensors (tensor picked by blockIdx.z).
__global__ __launch_bounds__(THREADS)
void skel_step_kernel(const float* __restrict__ src0, const float* __restrict__ src1,
                      float* __restrict__ dst)
{
    __shared__ float sx[SY*SX];
    __shared__ float sm[MY*MX];

    const int t = blockIdx.z / BATCH;
    const int b = blockIdx.z % BATCH;
    const float* src = (t == 0 ? src0 : src1) + b * NIMG;
    float* out = dst + t * NTEN + b * NIMG;

    const int x0 = blockIdx.x * TX - 2;
    const int y0 = blockIdx.y * TY - 2;
    load_and_minpool(src, sx, sm, x0, y0);

    const int tid = threadIdx.x;
    const int txx = tid & 31, tyy = tid >> 5;
    for (int r = tyy; r < TY; r += 8) {
        const int gy = blockIdx.y * TY + r;
        float* orow = out + gy * WW + blockIdx.x * TX;
        #pragma unroll
        for (int c = txx; c < TX; c += 32)
            orow[c] = skel_out(sx, sm, r, c);
    }
}

// Final (20th) iteration fused with the reductions: never writes the skeleton,
// instead multiplies with the counterpart tensor and atomically accumulates.
__global__ __launch_bounds__(THREADS)
void skel_final_kernel(const float* __restrict__ src0, const float* __restrict__ src1,
                       const float* __restrict__ other0, const float* __restrict__ other1)
{
    __shared__ float sx[SY*SX];
    __shared__ float sm[MY*MX];
    __shared__ float wprod[8], wsum[8];

    const int t = blockIdx.z / BATCH;
    const int b = blockIdx.z % BATCH;
    const float* src   = (t == 0 ? src0   : src1)   + b * NIMG;
    const float* other = (t == 0 ? other0 : other1) + b * NIMG;

    const int x0 = blockIdx.x * TX - 2;
    const int y0 = blockIdx.y * TY - 2;
    load_and_minpool(src, sx, sm, x0, y0);

    const int tid = threadIdx.x;
    const int txx = tid & 31, tyy = tid >> 5;
    float s_prod = 0.0f, s_sum = 0.0f;
    for (int r = tyy; r < TY; r += 8) {
        const int gy = blockIdx.y * TY + r;
        const float* orow = other + gy * WW + blockIdx.x * TX;
        #pragma unroll
        for (int c = txx; c < TX; c += 32) {
            float v = skel_out(sx, sm, r, c);
            s_prod += v * orow[c];
            s_sum  += v;
        }
    }

    // warp reduce
    #pragma unroll
    for (int off = 16; off; off >>= 1) {
        s_prod += __shfl_down_sync(0xffffffffu, s_prod, off);
        s_sum  += __shfl_down_sync(0xffffffffu, s_sum,  off);
    }
    if ((tid & 31) == 0) { wprod[tid >> 5] = s_prod; wsum[tid >> 5] = s_sum; }
    __syncthreads();
    if (tid == 0) {
        double p = 0.0, s = 0.0;
        #pragma unroll
        for (int i = 0; i < 8; i++) { p += (double)wprod[i]; s += (double)wsum[i]; }
        atomicAdd(&g_acc[t*2 + 0], p);
        atomicAdd(&g_acc[t*2 + 1], s);
    }
}

__global__ void finish_kernel(float* __restrict__ out)
{
    double iflat = (g_acc[0] + 1.0) / (g_acc[1] + 1.0);
    double tflat = (g_acc[2] + 1.0) / (g_acc[3] + 1.0);
    double loss  = 1.0 - 2.0 * iflat * tflat / (iflat + tflat);
    out[0] = (float)loss;
}

extern "C" void kernel_launch(void* const* d_in, const int* in_sizes, int n_in,
                              void* d_out, int out_size)
{
    const float* pred = (const float*)d_in[0];
    const float* gt   = (const float*)d_in[1];
    float* out = (float*)d_out;

    float *b0 = nullptr, *b1 = nullptr;
    cudaGetSymbolAddress((void**)&b0, g_buf0);
    cudaGetSymbolAddress((void**)&b1, g_buf1);

    dim3 grid(WW / TX, HH / TY, 2 * BATCH);

    zero_acc_kernel<<<1, 32>>>();

    // Iteration 0 reads the harness inputs.
    skel_step_kernel<<<grid, THREADS>>>(pred, gt, b0);

    // Iterations 1..18 ping-pong the scratch buffers.
    float* cur = b0;
    float* nxt = b1;
    for (int i = 1; i < 19; i++) {
        skel_step_kernel<<<grid, THREADS>>>(cur, cur + NTEN, nxt);
        float* tmp = cur; cur = nxt; nxt = tmp;
    }

    // Iteration 19 fused with the reductions (no skeleton write).
    skel_final_kernel<<<grid, THREADS>>>(cur, cur + NTEN, gt, pred);

    finish_kernel<<<1, 1>>>(out);
}